// round 1
// baseline (speedup 1.0000x reference)
#include <cuda_runtime.h>
#include <cstdint>

// ---------------- problem-size constants (padded maxima for static scratch) ---
constexpr int NMAX = 50048;       // >= 50000 nodes
constexpr int EMAX = 1600000;     // edges
constexpr int HID  = 128;         // hidden width (both layers use 128 cols)

// ---------------- static device scratch (no allocations allowed) -------------
__device__ int   g_deg[NMAX];
__device__ float g_dinv[NMAX];
__device__ int   g_rowstart[NMAX + 1];
__device__ int   g_cursor[NMAX];
__device__ int   g_csr_src[EMAX];
__device__ float g_H1[(size_t)NMAX * HID];   // x@W1, later relu(h)
__device__ float g_P1[(size_t)NMAX * HID];   // aggregated layer 1
__device__ float g_H2[(size_t)NMAX * HID];   // h@[Wmu|Wls]
__device__ float g_P2[(size_t)NMAX * HID];   // aggregated layer 2
__device__ float g_W2[HID * HID];            // concat(W_mu, W_ls)

// ---------------- small helper kernels ---------------------------------------
__global__ void k_zero_deg(int N) {
    int i = blockIdx.x * blockDim.x + threadIdx.x;
    if (i < N) g_deg[i] = 0;
}

__global__ void k_hist(const int* __restrict__ dst, int E) {
    int i = blockIdx.x * blockDim.x + threadIdx.x;
    if (i < E) atomicAdd(&g_deg[dst[i]], 1);
}

// single-block exclusive scan over deg -> rowstart, cursor
__global__ void k_scan(int N) {
    __shared__ int partial[1024];
    int t = threadIdx.x;
    int chunk = (N + 1023) / 1024;
    int begin = t * chunk;
    int end = begin + chunk; if (end > N) end = N;
    int s = 0;
    for (int i = begin; i < end; i++) s += g_deg[i];
    partial[t] = s;
    __syncthreads();
    if (t == 0) {
        int run = 0;
        for (int i = 0; i < 1024; i++) { int v = partial[i]; partial[i] = run; run += v; }
        g_rowstart[N] = run;
    }
    __syncthreads();
    int run = partial[t];
    for (int i = begin; i < end; i++) {
        g_rowstart[i] = run;
        g_cursor[i] = run;
        run += g_deg[i];
    }
}

__global__ void k_scatter(const int* __restrict__ src, const int* __restrict__ dst, int E) {
    int i = blockIdx.x * blockDim.x + threadIdx.x;
    if (i < E) {
        int d = dst[i];
        int pos = atomicAdd(&g_cursor[d], 1);
        g_csr_src[pos] = src[i];
    }
}

__global__ void k_dinv(int N) {
    int i = blockIdx.x * blockDim.x + threadIdx.x;
    if (i < N) g_dinv[i] = rsqrtf((float)(g_deg[i] + 1));   // +1 self-loop
}

__global__ void k_w2cat(const float* __restrict__ Wmu, const float* __restrict__ Wls) {
    int i = blockIdx.x * blockDim.x + threadIdx.x;
    if (i < HID * HID) {
        int k = i >> 7, c = i & 127;
        g_W2[i] = (c < 64) ? Wmu[k * 64 + c] : Wls[k * 64 + (c - 64)];
    }
}

__global__ void k_relu_bias(int total, const float* __restrict__ b) {
    int i = blockIdx.x * blockDim.x + threadIdx.x;
    if (i < total) {
        float v = g_P1[i] + __ldg(&b[i & 127]);
        g_H1[i] = v > 0.0f ? v : 0.0f;
    }
}

__global__ void k_epilogue(int N, const float* __restrict__ bmu, const float* __restrict__ bls,
                           float* __restrict__ out) {
    int i = blockIdx.x * blockDim.x + threadIdx.x;
    if (i < N * HID) {
        int n = i >> 7, c = i & 127;
        float v = g_P2[i];
        if (c < 64) out[(size_t)n * 64 + c] = v + __ldg(&bmu[c]);
        else        out[(size_t)N * 64 + (size_t)n * 64 + (c - 64)] = v + __ldg(&bls[c - 64]);
    }
}

// ---------------- gather-based GCN aggregation: one warp per node ------------
// P[d,:] = dinv[d]^2 * H[d,:] + sum_{edges s->d} dinv[s]*dinv[d] * H[s,:]
__global__ __launch_bounds__(256) void k_agg(int N, const float* __restrict__ H,
                                             float* __restrict__ P) {
    int warp = (blockIdx.x * blockDim.x + threadIdx.x) >> 5;
    int lane = threadIdx.x & 31;
    if (warp >= N) return;
    const int node = warp;
    const float4* __restrict__ H4 = (const float4*)H;

    float di = g_dinv[node];
    float4 self = H4[(size_t)node * 32 + lane];
    float w0 = di * di;
    float4 acc;
    acc.x = self.x * w0; acc.y = self.y * w0; acc.z = self.z * w0; acc.w = self.w * w0;

    int beg = g_rowstart[node];
    int end = g_rowstart[node + 1];
    for (int e = beg; e < end; e++) {
        int s = g_csr_src[e];
        float w = di * g_dinv[s];
        float4 v = __ldg(&H4[(size_t)s * 32 + lane]);
        acc.x += w * v.x; acc.y += w * v.y; acc.z += w * v.z; acc.w += w * v.w;
    }
    ((float4*)P)[(size_t)node * 32 + lane] = acc;
}

// ---------------- f32 SGEMM: C[M,128] = A[M,K] @ B[K,128] --------------------
// BM=128, BN=128(full), BK=16, TM=TN=8, 256 threads
__global__ __launch_bounds__(256) void k_sgemm(int M, int K,
                                               const float* __restrict__ A,
                                               const float* __restrict__ B,
                                               float* __restrict__ C) {
    constexpr int BM = 128, BN = 128, BK = 16, TM = 8, TN = 8;
    __shared__ float As[BK][BM];
    __shared__ float Bs[BK][BN];

    const int block_row = blockIdx.x * BM;
    const int tid = threadIdx.x;
    const int tx = tid & 15, ty = tid >> 4;

    const int aRow  = tid >> 2;          // 0..63
    const int aCol4 = (tid & 3) * 4;     // 0,4,8,12
    const int bRow  = tid >> 5;          // 0..7
    const int bCol4 = (tid & 31) * 4;    // 0..124

    float acc[TM][TN] = {};
    float regM[TM], regN[TN];

    for (int k0 = 0; k0 < K; k0 += BK) {
        #pragma unroll
        for (int i = 0; i < 2; i++) {
            int r = aRow + i * 64;
            int gr = block_row + r;
            float4 v = make_float4(0.f, 0.f, 0.f, 0.f);
            if (gr < M) v = *(const float4*)&A[(size_t)gr * K + k0 + aCol4];
            As[aCol4 + 0][r] = v.x;
            As[aCol4 + 1][r] = v.y;
            As[aCol4 + 2][r] = v.z;
            As[aCol4 + 3][r] = v.w;
        }
        #pragma unroll
        for (int i = 0; i < 2; i++) {
            int r = bRow + i * 8;
            *(float4*)&Bs[r][bCol4] = *(const float4*)&B[(size_t)(k0 + r) * BN + bCol4];
        }
        __syncthreads();
        #pragma unroll
        for (int k = 0; k < BK; k++) {
            #pragma unroll
            for (int i = 0; i < TM; i++) regM[i] = As[k][ty * TM + i];
            #pragma unroll
            for (int j = 0; j < TN; j++) regN[j] = Bs[k][tx * TN + j];
            #pragma unroll
            for (int i = 0; i < TM; i++)
                #pragma unroll
                for (int j = 0; j < TN; j++)
                    acc[i][j] += regM[i] * regN[j];
        }
        __syncthreads();
    }
    #pragma unroll
    for (int i = 0; i < TM; i++) {
        int gr = block_row + ty * TM + i;
        if (gr < M) {
            #pragma unroll
            for (int j = 0; j < TN; j += 4) {
                *(float4*)&C[(size_t)gr * BN + tx * TN + j] =
                    make_float4(acc[i][j], acc[i][j + 1], acc[i][j + 2], acc[i][j + 3]);
            }
        }
    }
}

// ---------------- launch ------------------------------------------------------
extern "C" void kernel_launch(void* const* d_in, const int* in_sizes, int n_in,
                              void* d_out, int out_size) {
    const float* x  = (const float*)d_in[0];
    const int*   ei = (const int*)d_in[1];
    // n_nodes may or may not be materialized as a 1-element tensor at index 2
    int base = (n_in >= 9 && in_sizes[2] == 1) ? 3 : 2;
    const float* W1  = (const float*)d_in[base + 0];
    const float* b1  = (const float*)d_in[base + 1];
    const float* Wmu = (const float*)d_in[base + 2];
    const float* bmu = (const float*)d_in[base + 3];
    const float* Wls = (const float*)d_in[base + 4];
    const float* bls = (const float*)d_in[base + 5];
    float* out = (float*)d_out;

    const int N = in_sizes[0] / 256;   // 50000
    const int E = in_sizes[1] / 2;     // 1600000
    const int* src = ei;
    const int* dst = ei + E;

    float *pH1, *pP1, *pH2, *pP2;
    cudaGetSymbolAddress((void**)&pH1, g_H1);
    cudaGetSymbolAddress((void**)&pP1, g_P1);
    cudaGetSymbolAddress((void**)&pH2, g_H2);
    cudaGetSymbolAddress((void**)&pP2, g_P2);
    float* pW2;
    cudaGetSymbolAddress((void**)&pW2, g_W2);

    const int T = 256;
    // ---- CSR build (shared by both layers) ----
    k_zero_deg<<<(N + T - 1) / T, T>>>(N);
    k_hist<<<(E + T - 1) / T, T>>>(dst, E);
    k_scan<<<1, 1024>>>(N);
    k_scatter<<<(E + T - 1) / T, T>>>(src, dst, E);
    k_dinv<<<(N + T - 1) / T, T>>>(N);

    // ---- layer 1: H1 = x @ W1 ; P1 = A_norm @ H1 ; h = relu(P1 + b1) ----
    k_sgemm<<<(N + 127) / 128, 256>>>(N, 256, x, W1, pH1);
    k_agg<<<(N * 32 + T - 1) / T, T>>>(N, pH1, pP1);
    k_relu_bias<<<(N * HID + T - 1) / T, T>>>(N * HID, b1);

    // ---- layer 2 (mu & logstd fused): H2 = h @ [Wmu|Wls] ; P2 = A_norm @ H2 ----
    k_w2cat<<<(HID * HID + T - 1) / T, T>>>(Wmu, Wls);
    k_sgemm<<<(N + 127) / 128, 256>>>(N, 128, pH1, pW2, pH2);
    k_agg<<<(N * 32 + T - 1) / T, T>>>(N, pH2, pP2);

    // ---- split into (mu, logstd) with biases ----
    k_epilogue<<<(N * HID + T - 1) / T, T>>>(N, bmu, bls, out);
}

// round 4
// speedup vs baseline: 1.2349x; 1.2349x over previous
#include <cuda_runtime.h>
#include <cuda_fp16.h>
#include <cstdint>

// ---------------- problem-size constants (padded maxima for static scratch) ---
constexpr int NMAX = 50048;       // >= 50000 nodes
constexpr int EMAX = 1600000;     // edges
constexpr int HID  = 128;         // hidden width (both layers use 128 cols)

// ---------------- static device scratch (no allocations allowed) -------------
__device__ int    g_deg[NMAX];
__device__ float  g_dinv[NMAX];
__device__ int    g_rowstart[NMAX + 1];
__device__ int    g_rank[EMAX];
__device__ int    g_csr_src[EMAX];
__device__ __half g_Hs1[(size_t)NMAX * HID];  // dinv-scaled x@W1, fp16
__device__ float  g_h[(size_t)NMAX * HID];    // hidden activations fp32 (GEMM2 input)
__device__ __half g_Hs2[(size_t)NMAX * HID];  // dinv-scaled h@[Wmu|Wls], fp16
__device__ float  g_W2[HID * HID];            // concat(W_mu, W_ls)

// ---------------- CSR build ---------------------------------------------------
__global__ void k_zero_deg(int N) {
    int i = blockIdx.x * blockDim.x + threadIdx.x;
    if (i < N) g_deg[i] = 0;
}

// histogram; remember each edge's rank within its destination bucket
__global__ void k_hist_rank(const int* __restrict__ dst, int E) {
    int i = blockIdx.x * blockDim.x + threadIdx.x;
    if (i < E) g_rank[i] = atomicAdd(&g_deg[dst[i]], 1);
}

// single-block exclusive scan over deg -> rowstart; also computes dinv
__global__ void k_scan(int N) {
    __shared__ int partial[1024];
    int t = threadIdx.x;
    int chunk = (N + 1023) / 1024;
    int begin = t * chunk;
    int end = begin + chunk; if (end > N) end = N;
    int s = 0;
    for (int i = begin; i < end; i++) s += g_deg[i];
    partial[t] = s;
    __syncthreads();
    if (t == 0) {
        int run = 0;
        for (int i = 0; i < 1024; i++) { int v = partial[i]; partial[i] = run; run += v; }
        g_rowstart[N] = run;
    }
    __syncthreads();
    int run = partial[t];
    for (int i = begin; i < end; i++) {
        g_rowstart[i] = run;
        run += g_deg[i];
        g_dinv[i] = rsqrtf((float)(g_deg[i] + 1));   // +1 self-loop
    }
}

// atomic-free scatter using precomputed ranks
__global__ void k_scatter(const int* __restrict__ src, const int* __restrict__ dst, int E) {
    int i = blockIdx.x * blockDim.x + threadIdx.x;
    if (i < E) g_csr_src[g_rowstart[dst[i]] + g_rank[i]] = src[i];
}

__global__ void k_w2cat(const float* __restrict__ Wmu, const float* __restrict__ Wls) {
    int i = blockIdx.x * blockDim.x + threadIdx.x;
    if (i < HID * HID) {
        int k = i >> 7, c = i & 127;
        g_W2[i] = (c < 64) ? Wmu[k * 64 + c] : Wls[k * 64 + (c - 64)];
    }
}

// ---------------- helpers ------------------------------------------------------
__device__ __forceinline__ void acc_h4(float4& a, uint2 u) {
    float2 lo = __half22float2(*reinterpret_cast<__half2*>(&u.x));
    float2 hi = __half22float2(*reinterpret_cast<__half2*>(&u.y));
    a.x += lo.x; a.y += lo.y; a.z += hi.x; a.w += hi.y;
}

// ---------------- aggregation (fp16 gather), one warp per node -----------------
// P[d,:] = dinv[d] * ( Hs[d,:] + sum_{edges s->d} Hs[s,:] )
// layer 1 variant: h = relu(P + b1), write fp32
__global__ __launch_bounds__(256) void k_agg_relu(int N, const float* __restrict__ b) {
    int warp = (blockIdx.x * blockDim.x + threadIdx.x) >> 5;
    int lane = threadIdx.x & 31;
    if (warp >= N) return;
    const int node = warp;
    const uint2* __restrict__ Hs4 = (const uint2*)g_Hs1;

    uint2 self = Hs4[(size_t)node * 32 + lane];
    float4 acc = make_float4(0.f, 0.f, 0.f, 0.f);
    acc_h4(acc, self);

    int e = g_rowstart[node];
    const int end = g_rowstart[node + 1];
    for (; e + 4 <= end; e += 4) {
        int s0 = g_csr_src[e + 0], s1 = g_csr_src[e + 1];
        int s2 = g_csr_src[e + 2], s3 = g_csr_src[e + 3];
        uint2 u0 = __ldg(&Hs4[(size_t)s0 * 32 + lane]);
        uint2 u1 = __ldg(&Hs4[(size_t)s1 * 32 + lane]);
        uint2 u2 = __ldg(&Hs4[(size_t)s2 * 32 + lane]);
        uint2 u3 = __ldg(&Hs4[(size_t)s3 * 32 + lane]);
        acc_h4(acc, u0); acc_h4(acc, u1); acc_h4(acc, u2); acc_h4(acc, u3);
    }
    for (; e < end; e++) {
        uint2 u = __ldg(&Hs4[(size_t)g_csr_src[e] * 32 + lane]);
        acc_h4(acc, u);
    }

    float di = g_dinv[node];
    int c = lane * 4;
    float4 bb = *(const float4*)&b[c];
    float4 r;
    r.x = fmaxf(acc.x * di + bb.x, 0.f);
    r.y = fmaxf(acc.y * di + bb.y, 0.f);
    r.z = fmaxf(acc.z * di + bb.z, 0.f);
    r.w = fmaxf(acc.w * di + bb.w, 0.f);
    ((float4*)g_h)[(size_t)node * 32 + lane] = r;
}

// layer 2 variant: split into (mu, logstd) halves with biases, write to output
__global__ __launch_bounds__(256) void k_agg_out(int N, const float* __restrict__ bmu,
                                                 const float* __restrict__ bls,
                                                 float* __restrict__ out) {
    int warp = (blockIdx.x * blockDim.x + threadIdx.x) >> 5;
    int lane = threadIdx.x & 31;
    if (warp >= N) return;
    const int node = warp;
    const uint2* __restrict__ Hs4 = (const uint2*)g_Hs2;

    uint2 self = Hs4[(size_t)node * 32 + lane];
    float4 acc = make_float4(0.f, 0.f, 0.f, 0.f);
    acc_h4(acc, self);

    int e = g_rowstart[node];
    const int end = g_rowstart[node + 1];
    for (; e + 4 <= end; e += 4) {
        int s0 = g_csr_src[e + 0], s1 = g_csr_src[e + 1];
        int s2 = g_csr_src[e + 2], s3 = g_csr_src[e + 3];
        uint2 u0 = __ldg(&Hs4[(size_t)s0 * 32 + lane]);
        uint2 u1 = __ldg(&Hs4[(size_t)s1 * 32 + lane]);
        uint2 u2 = __ldg(&Hs4[(size_t)s2 * 32 + lane]);
        uint2 u3 = __ldg(&Hs4[(size_t)s3 * 32 + lane]);
        acc_h4(acc, u0); acc_h4(acc, u1); acc_h4(acc, u2); acc_h4(acc, u3);
    }
    for (; e < end; e++) {
        uint2 u = __ldg(&Hs4[(size_t)g_csr_src[e] * 32 + lane]);
        acc_h4(acc, u);
    }

    float di = g_dinv[node];
    int c = lane * 4;   // 0..124
    float4 r;
    if (c < 64) {
        float4 bb = *(const float4*)&bmu[c];
        r.x = acc.x * di + bb.x; r.y = acc.y * di + bb.y;
        r.z = acc.z * di + bb.z; r.w = acc.w * di + bb.w;
        *(float4*)&out[(size_t)node * 64 + c] = r;
    } else {
        float4 bb = *(const float4*)&bls[c - 64];
        r.x = acc.x * di + bb.x; r.y = acc.y * di + bb.y;
        r.z = acc.z * di + bb.z; r.w = acc.w * di + bb.w;
        *(float4*)&out[(size_t)N * 64 + (size_t)node * 64 + (c - 64)] = r;
    }
}

// ---------------- f32 SGEMM: Hs[M,128] = fp16(dinv[m] * (A[M,K] @ B[K,128])) ---
// BM=128, BN=128(full), BK=16, TM=TN=8, 256 threads
__global__ __launch_bounds__(256) void k_sgemm_h(int M, int K,
                                                 const float* __restrict__ A,
                                                 const float* __restrict__ B,
                                                 __half* __restrict__ Hs) {
    constexpr int BM = 128, BN = 128, BK = 16, TM = 8, TN = 8;
    __shared__ float As[BK][BM];
    __shared__ float Bs[BK][BN];

    const int block_row = blockIdx.x * BM;
    const int tid = threadIdx.x;
    const int tx = tid & 15, ty = tid >> 4;

    const int aRow  = tid >> 2;          // 0..63
    const int aCol4 = (tid & 3) * 4;     // 0,4,8,12
    const int bRow  = tid >> 5;          // 0..7
    const int bCol4 = (tid & 31) * 4;    // 0..124

    float acc[TM][TN] = {};
    float regM[TM], regN[TN];

    for (int k0 = 0; k0 < K; k0 += BK) {
        #pragma unroll
        for (int i = 0; i < 2; i++) {
            int r = aRow + i * 64;
            int gr = block_row + r;
            float4 v = make_float4(0.f, 0.f, 0.f, 0.f);
            if (gr < M) v = *(const float4*)&A[(size_t)gr * K + k0 + aCol4];
            As[aCol4 + 0][r] = v.x;
            As[aCol4 + 1][r] = v.y;
            As[aCol4 + 2][r] = v.z;
            As[aCol4 + 3][r] = v.w;
        }
        #pragma unroll
        for (int i = 0; i < 2; i++) {
            int r = bRow + i * 8;
            *(float4*)&Bs[r][bCol4] = *(const float4*)&B[(size_t)(k0 + r) * BN + bCol4];
        }
        __syncthreads();
        #pragma unroll
        for (int k = 0; k < BK; k++) {
            #pragma unroll
            for (int i = 0; i < TM; i++) regM[i] = As[k][ty * TM + i];
            #pragma unroll
            for (int j = 0; j < TN; j++) regN[j] = Bs[k][tx * TN + j];
            #pragma unroll
            for (int i = 0; i < TM; i++)
                #pragma unroll
                for (int j = 0; j < TN; j++)
                    acc[i][j] += regM[i] * regN[j];
        }
        __syncthreads();
    }
    #pragma unroll
    for (int i = 0; i < TM; i++) {
        int gr = block_row + ty * TM + i;
        if (gr < M) {
            float di = g_dinv[gr];
            #pragma unroll
            for (int j = 0; j < TN; j += 4) {
                __half2 h0 = __float22half2_rn(make_float2(acc[i][j] * di, acc[i][j + 1] * di));
                __half2 h1 = __float22half2_rn(make_float2(acc[i][j + 2] * di, acc[i][j + 3] * di));
                uint2 pack;
                pack.x = *reinterpret_cast<unsigned*>(&h0);
                pack.y = *reinterpret_cast<unsigned*>(&h1);
                *(uint2*)&Hs[(size_t)gr * BN + tx * TN + j] = pack;
            }
        }
    }
}

// ---------------- launch ------------------------------------------------------
extern "C" void kernel_launch(void* const* d_in, const int* in_sizes, int n_in,
                              void* d_out, int out_size) {
    const float* x  = (const float*)d_in[0];
    const int*   ei = (const int*)d_in[1];
    int base = (n_in >= 9 && in_sizes[2] == 1) ? 3 : 2;
    const float* W1  = (const float*)d_in[base + 0];
    const float* b1  = (const float*)d_in[base + 1];
    const float* Wmu = (const float*)d_in[base + 2];
    const float* bmu = (const float*)d_in[base + 3];
    const float* Wls = (const float*)d_in[base + 4];
    const float* bls = (const float*)d_in[base + 5];
    float* out = (float*)d_out;

    const int N = in_sizes[0] / 256;   // 50000
    const int E = in_sizes[1] / 2;     // 1600000
    const int* src = ei;
    const int* dst = ei + E;

    float *ph, *pW2;
    __half *pHs1, *pHs2;
    cudaGetSymbolAddress((void**)&pHs1, g_Hs1);
    cudaGetSymbolAddress((void**)&ph,   g_h);
    cudaGetSymbolAddress((void**)&pHs2, g_Hs2);
    cudaGetSymbolAddress((void**)&pW2,  g_W2);

    const int T = 256;
    // ---- CSR build (shared by both layers) ----
    k_zero_deg<<<(N + T - 1) / T, T>>>(N);
    k_hist_rank<<<(E + T - 1) / T, T>>>(dst, E);
    k_scan<<<1, 1024>>>(N);                       // rowstart + dinv
    k_scatter<<<(E + T - 1) / T, T>>>(src, dst, E);
    k_w2cat<<<(HID * HID + T - 1) / T, T>>>(Wmu, Wls);

    // ---- layer 1: Hs1 = fp16(dinv .* (x@W1)); h = relu(dinv .* agg(Hs1) + b1) ----
    k_sgemm_h<<<(N + 127) / 128, 256>>>(N, 256, x, W1, pHs1);
    k_agg_relu<<<(N * 32 + T - 1) / T, T>>>(N, b1);

    // ---- layer 2 (mu & logstd fused): Hs2 = fp16(dinv .* (h@[Wmu|Wls])) ----
    k_sgemm_h<<<(N + 127) / 128, 256>>>(N, 128, ph, pW2, pHs2);
    k_agg_out<<<(N * 32 + T - 1) / T, T>>>(N, bmu, bls, out);
}

// round 5
// speedup vs baseline: 1.5968x; 1.2931x over previous
#include <cuda_runtime.h>
#include <cuda_fp16.h>
#include <mma.h>
#include <cstdint>

using namespace nvcuda;

// ---------------- problem-size constants (padded maxima for static scratch) ---
constexpr int NMAX = 50048;       // >= 50000 nodes
constexpr int EMAX = 1600000;     // edges
constexpr int HID  = 128;         // hidden width (both layers use 128 cols)

// ---------------- static device scratch (no allocations allowed) -------------
__device__ int    g_deg[NMAX];
__device__ float  g_dinv[NMAX];
__device__ int    g_rowstart[NMAX + 1];
__device__ int    g_rank[EMAX];
__device__ int    g_csr_src[EMAX];
__device__ __half g_Hs1[(size_t)NMAX * HID];  // dinv-scaled x@W1, fp16
__device__ __half g_hh[(size_t)NMAX * HID];   // hidden activations fp16 (GEMM2 A)
__device__ __half g_Hs2[(size_t)NMAX * HID];  // dinv-scaled h@[Wmu|Wls], fp16
__device__ __half g_W1h[256 * HID];           // W1 fp16
__device__ __half g_W2h[HID * HID];           // concat(W_mu, W_ls) fp16

// ---------------- CSR build ---------------------------------------------------
__global__ void k_zero_deg(int N) {
    int i = blockIdx.x * blockDim.x + threadIdx.x;
    if (i < N) g_deg[i] = 0;
}

__global__ void k_hist_rank(const int* __restrict__ dst, int E) {
    int i = blockIdx.x * blockDim.x + threadIdx.x;
    if (i < E) g_rank[i] = atomicAdd(&g_deg[dst[i]], 1);
}

// single-block exclusive scan over deg -> rowstart; also computes dinv
__global__ void k_scan(int N) {
    __shared__ int partial[1024];
    int t = threadIdx.x;
    int chunk = (N + 1023) / 1024;
    int begin = t * chunk;
    int end = begin + chunk; if (end > N) end = N;
    int s = 0;
    for (int i = begin; i < end; i++) s += g_deg[i];
    partial[t] = s;
    __syncthreads();
    if (t == 0) {
        int run = 0;
        for (int i = 0; i < 1024; i++) { int v = partial[i]; partial[i] = run; run += v; }
        g_rowstart[N] = run;
    }
    __syncthreads();
    int run = partial[t];
    for (int i = begin; i < end; i++) {
        g_rowstart[i] = run;
        run += g_deg[i];
        g_dinv[i] = rsqrtf((float)(g_deg[i] + 1));   // +1 self-loop
    }
}

__global__ void k_scatter(const int* __restrict__ src, const int* __restrict__ dst, int E) {
    int i = blockIdx.x * blockDim.x + threadIdx.x;
    if (i < E) g_csr_src[g_rowstart[dst[i]] + g_rank[i]] = src[i];
}

__global__ void k_w1h(const float* __restrict__ W1) {
    int i = blockIdx.x * blockDim.x + threadIdx.x;
    if (i < 256 * HID) g_W1h[i] = __float2half_rn(W1[i]);
}

__global__ void k_w2cat(const float* __restrict__ Wmu, const float* __restrict__ Wls) {
    int i = blockIdx.x * blockDim.x + threadIdx.x;
    if (i < HID * HID) {
        int k = i >> 7, c = i & 127;
        g_W2h[i] = __float2half_rn((c < 64) ? Wmu[k * 64 + c] : Wls[k * 64 + (c - 64)]);
    }
}

// ---------------- helpers ------------------------------------------------------
__device__ __forceinline__ void acc_h4(float4& a, uint2 u) {
    float2 lo = __half22float2(*reinterpret_cast<__half2*>(&u.x));
    float2 hi = __half22float2(*reinterpret_cast<__half2*>(&u.y));
    a.x += lo.x; a.y += lo.y; a.z += hi.x; a.w += hi.y;
}

// ---------------- aggregation (fp16 gather), one warp per node -----------------
// P[d,:] = dinv[d] * ( Hs[d,:] + sum_{edges s->d} Hs[s,:] )
// layer 1 variant: h = relu(P + b1), write fp16 (feeds tensor-core GEMM2)
__global__ __launch_bounds__(256) void k_agg_relu(int N, const float* __restrict__ b) {
    int warp = (blockIdx.x * blockDim.x + threadIdx.x) >> 5;
    int lane = threadIdx.x & 31;
    if (warp >= N) return;
    const int node = warp;
    const uint2* __restrict__ Hs4 = (const uint2*)g_Hs1;

    uint2 self = Hs4[(size_t)node * 32 + lane];
    float4 acc = make_float4(0.f, 0.f, 0.f, 0.f);
    acc_h4(acc, self);

    int e = g_rowstart[node];
    const int end = g_rowstart[node + 1];
    for (; e + 4 <= end; e += 4) {
        int s0 = g_csr_src[e + 0], s1 = g_csr_src[e + 1];
        int s2 = g_csr_src[e + 2], s3 = g_csr_src[e + 3];
        uint2 u0 = __ldg(&Hs4[(size_t)s0 * 32 + lane]);
        uint2 u1 = __ldg(&Hs4[(size_t)s1 * 32 + lane]);
        uint2 u2 = __ldg(&Hs4[(size_t)s2 * 32 + lane]);
        uint2 u3 = __ldg(&Hs4[(size_t)s3 * 32 + lane]);
        acc_h4(acc, u0); acc_h4(acc, u1); acc_h4(acc, u2); acc_h4(acc, u3);
    }
    for (; e < end; e++) {
        uint2 u = __ldg(&Hs4[(size_t)g_csr_src[e] * 32 + lane]);
        acc_h4(acc, u);
    }

    float di = g_dinv[node];
    int c = lane * 4;
    float4 bb = *(const float4*)&b[c];
    __half2 h0 = __float22half2_rn(make_float2(fmaxf(acc.x * di + bb.x, 0.f),
                                               fmaxf(acc.y * di + bb.y, 0.f)));
    __half2 h1 = __float22half2_rn(make_float2(fmaxf(acc.z * di + bb.z, 0.f),
                                               fmaxf(acc.w * di + bb.w, 0.f)));
    uint2 pack;
    pack.x = *reinterpret_cast<unsigned*>(&h0);
    pack.y = *reinterpret_cast<unsigned*>(&h1);
    ((uint2*)g_hh)[(size_t)node * 32 + lane] = pack;
}

// layer 2 variant: split into (mu, logstd) halves with biases, write to output
__global__ __launch_bounds__(256) void k_agg_out(int N, const float* __restrict__ bmu,
                                                 const float* __restrict__ bls,
                                                 float* __restrict__ out) {
    int warp = (blockIdx.x * blockDim.x + threadIdx.x) >> 5;
    int lane = threadIdx.x & 31;
    if (warp >= N) return;
    const int node = warp;
    const uint2* __restrict__ Hs4 = (const uint2*)g_Hs2;

    uint2 self = Hs4[(size_t)node * 32 + lane];
    float4 acc = make_float4(0.f, 0.f, 0.f, 0.f);
    acc_h4(acc, self);

    int e = g_rowstart[node];
    const int end = g_rowstart[node + 1];
    for (; e + 4 <= end; e += 4) {
        int s0 = g_csr_src[e + 0], s1 = g_csr_src[e + 1];
        int s2 = g_csr_src[e + 2], s3 = g_csr_src[e + 3];
        uint2 u0 = __ldg(&Hs4[(size_t)s0 * 32 + lane]);
        uint2 u1 = __ldg(&Hs4[(size_t)s1 * 32 + lane]);
        uint2 u2 = __ldg(&Hs4[(size_t)s2 * 32 + lane]);
        uint2 u3 = __ldg(&Hs4[(size_t)s3 * 32 + lane]);
        acc_h4(acc, u0); acc_h4(acc, u1); acc_h4(acc, u2); acc_h4(acc, u3);
    }
    for (; e < end; e++) {
        uint2 u = __ldg(&Hs4[(size_t)g_csr_src[e] * 32 + lane]);
        acc_h4(acc, u);
    }

    float di = g_dinv[node];
    int c = lane * 4;   // 0..124
    float4 r;
    if (c < 64) {
        float4 bb = *(const float4*)&bmu[c];
        r.x = acc.x * di + bb.x; r.y = acc.y * di + bb.y;
        r.z = acc.z * di + bb.z; r.w = acc.w * di + bb.w;
        *(float4*)&out[(size_t)node * 64 + c] = r;
    } else {
        float4 bb = *(const float4*)&bls[c - 64];
        r.x = acc.x * di + bb.x; r.y = acc.y * di + bb.y;
        r.z = acc.z * di + bb.z; r.w = acc.w * di + bb.w;
        *(float4*)&out[(size_t)N * 64 + (size_t)node * 64 + (c - 64)] = r;
    }
}

// ---------------- tensor-core GEMM: Hs[M,128] = fp16(dinv[m]*(A[M,K]@B[K,128]))
// BM=128, BN=128, BK=32. 256 threads = 8 warps in 4x2 grid; warp tile 32x64.
// A_IS_HALF=false: A fp32, converted on load. true: A fp16 passthrough.
template<bool A_IS_HALF>
__global__ __launch_bounds__(256) void k_hgemm(int M, int K,
                                               const void* __restrict__ Av,
                                               const __half* __restrict__ B,
                                               __half* __restrict__ Hs) {
    constexpr int BM = 128, BN = 128, BK = 32;
    __shared__ __align__(32) __half As[BM][BK + 8];
    __shared__ __align__(32) __half Bs[BK][BN + 8];
    __shared__ __align__(32) float  Cs[8][16][24];

    const int tid = threadIdx.x;
    const int wid = tid >> 5;
    const int lane = tid & 31;
    const int warp_m = wid >> 1;          // 0..3
    const int warp_n = wid & 1;           // 0..1
    const int block_row = blockIdx.x * BM;

    wmma::fragment<wmma::accumulator, 16, 16, 16, float> facc[2][4];
    #pragma unroll
    for (int i = 0; i < 2; i++)
        #pragma unroll
        for (int j = 0; j < 4; j++) wmma::fill_fragment(facc[i][j], 0.0f);

    for (int k0 = 0; k0 < K; k0 += BK) {
        // ---- load A tile (128 x 32) ----
        if (A_IS_HALF) {
            const __half* A = (const __half*)Av;
            #pragma unroll
            for (int i = 0; i < 4; i++) {
                int idx = tid + i * 256;          // 0..1023
                int r = idx >> 3, c4 = (idx & 7) * 4;
                int gr = block_row + r;
                uint2 v = make_uint2(0u, 0u);
                if (gr < M) v = *(const uint2*)&A[(size_t)gr * K + k0 + c4];
                *(uint2*)&As[r][c4] = v;
            }
        } else {
            const float* A = (const float*)Av;
            #pragma unroll
            for (int i = 0; i < 4; i++) {
                int idx = tid + i * 256;
                int r = idx >> 3, c4 = (idx & 7) * 4;
                int gr = block_row + r;
                float4 v = make_float4(0.f, 0.f, 0.f, 0.f);
                if (gr < M) v = *(const float4*)&A[(size_t)gr * K + k0 + c4];
                __half2 h0 = __float22half2_rn(make_float2(v.x, v.y));
                __half2 h1 = __float22half2_rn(make_float2(v.z, v.w));
                uint2 pack;
                pack.x = *reinterpret_cast<unsigned*>(&h0);
                pack.y = *reinterpret_cast<unsigned*>(&h1);
                *(uint2*)&As[r][c4] = pack;
            }
        }
        // ---- load B tile (32 x 128) ----
        #pragma unroll
        for (int i = 0; i < 4; i++) {
            int idx = tid + i * 256;              // 0..1023
            int r = idx >> 5, c4 = (idx & 31) * 4;
            *(uint2*)&Bs[r][c4] = *(const uint2*)&B[(size_t)(k0 + r) * BN + c4];
        }
        __syncthreads();

        #pragma unroll
        for (int kk = 0; kk < BK; kk += 16) {
            wmma::fragment<wmma::matrix_a, 16, 16, 16, __half, wmma::row_major> fa[2];
            wmma::fragment<wmma::matrix_b, 16, 16, 16, __half, wmma::row_major> fb[4];
            #pragma unroll
            for (int i = 0; i < 2; i++)
                wmma::load_matrix_sync(fa[i], &As[warp_m * 32 + i * 16][kk], BK + 8);
            #pragma unroll
            for (int j = 0; j < 4; j++)
                wmma::load_matrix_sync(fb[j], &Bs[kk][warp_n * 64 + j * 16], BN + 8);
            #pragma unroll
            for (int i = 0; i < 2; i++)
                #pragma unroll
                for (int j = 0; j < 4; j++)
                    wmma::mma_sync(facc[i][j], fa[i], fb[j], facc[i][j]);
        }
        __syncthreads();
    }

    // ---- epilogue: scale rows by dinv, convert fp16, store ----
    #pragma unroll
    for (int i = 0; i < 2; i++) {
        #pragma unroll
        for (int j = 0; j < 4; j++) {
            wmma::store_matrix_sync(&Cs[wid][0][0], facc[i][j], 24, wmma::mem_row_major);
            __syncwarp();
            int r = lane >> 1;
            int gr = block_row + warp_m * 32 + i * 16 + r;
            int col = warp_n * 64 + j * 16 + (lane & 1) * 8;
            if (gr < M) {
                float di = g_dinv[gr];
                float4 v0 = *(float4*)&Cs[wid][r][(lane & 1) * 8];
                float4 v1 = *(float4*)&Cs[wid][r][(lane & 1) * 8 + 4];
                __half2 h0 = __float22half2_rn(make_float2(v0.x * di, v0.y * di));
                __half2 h1 = __float22half2_rn(make_float2(v0.z * di, v0.w * di));
                __half2 h2 = __float22half2_rn(make_float2(v1.x * di, v1.y * di));
                __half2 h3 = __float22half2_rn(make_float2(v1.z * di, v1.w * di));
                uint4 pack;
                pack.x = *reinterpret_cast<unsigned*>(&h0);
                pack.y = *reinterpret_cast<unsigned*>(&h1);
                pack.z = *reinterpret_cast<unsigned*>(&h2);
                pack.w = *reinterpret_cast<unsigned*>(&h3);
                *(uint4*)&Hs[(size_t)gr * BN + col] = pack;
            }
            __syncwarp();
        }
    }
}

// ---------------- launch ------------------------------------------------------
extern "C" void kernel_launch(void* const* d_in, const int* in_sizes, int n_in,
                              void* d_out, int out_size) {
    const float* x  = (const float*)d_in[0];
    const int*   ei = (const int*)d_in[1];
    int base = (n_in >= 9 && in_sizes[2] == 1) ? 3 : 2;
    const float* W1  = (const float*)d_in[base + 0];
    const float* b1  = (const float*)d_in[base + 1];
    const float* Wmu = (const float*)d_in[base + 2];
    const float* bmu = (const float*)d_in[base + 3];
    const float* Wls = (const float*)d_in[base + 4];
    const float* bls = (const float*)d_in[base + 5];
    float* out = (float*)d_out;

    const int N = in_sizes[0] / 256;   // 50000
    const int E = in_sizes[1] / 2;     // 1600000
    const int* src = ei;
    const int* dst = ei + E;

    __half *pHs1, *pHs2, *phh, *pW1h, *pW2h;
    cudaGetSymbolAddress((void**)&pHs1, g_Hs1);
    cudaGetSymbolAddress((void**)&phh,  g_hh);
    cudaGetSymbolAddress((void**)&pHs2, g_Hs2);
    cudaGetSymbolAddress((void**)&pW1h, g_W1h);
    cudaGetSymbolAddress((void**)&pW2h, g_W2h);

    const int T = 256;
    // ---- CSR build (shared by both layers) ----
    k_zero_deg<<<(N + T - 1) / T, T>>>(N);
    k_hist_rank<<<(E + T - 1) / T, T>>>(dst, E);
    k_scan<<<1, 1024>>>(N);                       // rowstart + dinv
    k_scatter<<<(E + T - 1) / T, T>>>(src, dst, E);
    k_w1h<<<(256 * HID + T - 1) / T, T>>>(W1);
    k_w2cat<<<(HID * HID + T - 1) / T, T>>>(Wmu, Wls);

    // ---- layer 1: Hs1 = fp16(dinv .* (x@W1)); h = relu(dinv .* agg(Hs1) + b1) ----
    k_hgemm<false><<<(N + 127) / 128, 256>>>(N, 256, x, pW1h, pHs1);
    k_agg_relu<<<(N * 32 + T - 1) / T, T>>>(N, b1);

    // ---- layer 2 (mu & logstd fused): Hs2 = fp16(dinv .* (h@[Wmu|Wls])) ----
    k_hgemm<true><<<(N + 127) / 128, 256>>>(N, 128, phh, pW2h, pHs2);
    k_agg_out<<<(N * 32 + T - 1) / T, T>>>(N, bmu, bls, out);
}

// round 8
// speedup vs baseline: 2.4146x; 1.5121x over previous
#include <cuda_runtime.h>
#include <cuda_fp16.h>
#include <mma.h>
#include <cstdint>

using namespace nvcuda;

// ---------------- problem-size constants (padded maxima for static scratch) ---
constexpr int NMAX = 50048;       // >= 50000 nodes
constexpr int EMAX = 1600000;     // edges
constexpr int HID  = 128;         // hidden width (both layers use 128 cols)

// ---------------- static device scratch (no allocations allowed) -------------
__device__ int    g_deg[NMAX];
__device__ float  g_dinv[NMAX];
__device__ int    g_rowstart[NMAX + 1];
__device__ int    g_rank[EMAX];
__device__ int    g_csr_src[EMAX];
__device__ __half g_Hs1[(size_t)NMAX * HID];  // dinv-scaled x@W1, fp16
__device__ __half g_hh[(size_t)NMAX * HID];   // hidden activations fp16 (GEMM2 A)
__device__ __half g_Hs2[(size_t)NMAX * HID];  // dinv-scaled h@[Wmu|Wls], fp16
__device__ __half g_W1h[256 * HID];           // W1 fp16
__device__ __half g_W2h[HID * HID];           // concat(W_mu, W_ls) fp16

// ---------------- CSR build ---------------------------------------------------
__global__ void k_hist_rank(const int* __restrict__ dst, int E) {
    int i = blockIdx.x * blockDim.x + threadIdx.x;
    if (i < E) g_rank[i] = atomicAdd(&g_deg[dst[i]], 1);
}

__global__ void k_dinv(int N) {
    int i = blockIdx.x * blockDim.x + threadIdx.x;
    if (i < N) g_dinv[i] = rsqrtf((float)(g_deg[i] + 1));   // +1 self-loop
}

// single-block exclusive scan over deg -> rowstart (two-level shfl scan)
__global__ void k_scan(int N) {
    __shared__ int warp_tot[32];
    int t = threadIdx.x;
    int chunk = (N + 1023) / 1024;
    int begin = t * chunk;
    int end = begin + chunk; if (end > N) end = N;
    int s = 0;
    for (int i = begin; i < end; i++) s += g_deg[i];

    // inclusive warp scan
    int lane = t & 31, wid = t >> 5;
    int v = s;
    #pragma unroll
    for (int d = 1; d < 32; d <<= 1) {
        int n = __shfl_up_sync(0xffffffff, v, d);
        if (lane >= d) v += n;
    }
    if (lane == 31) warp_tot[wid] = v;
    __syncthreads();
    if (wid == 0) {
        int w = (lane < 32) ? warp_tot[lane] : 0;
        #pragma unroll
        for (int d = 1; d < 32; d <<= 1) {
            int n = __shfl_up_sync(0xffffffff, w, d);
            if (lane >= d) w += n;
        }
        warp_tot[lane] = w;
    }
    __syncthreads();
    int excl = v - s + (wid > 0 ? warp_tot[wid - 1] : 0);   // exclusive prefix for this thread

    int run = excl;
    for (int i = begin; i < end; i++) {
        g_rowstart[i] = run;
        run += g_deg[i];
    }
    if (t == 1023) g_rowstart[N] = run;
}

__global__ void k_scatter(const int* __restrict__ src, const int* __restrict__ dst, int E) {
    int i = blockIdx.x * blockDim.x + threadIdx.x;
    if (i < E) g_csr_src[g_rowstart[dst[i]] + g_rank[i]] = src[i];
}

// fused weight conversion: W1 (256x128) and [Wmu|Wls] (128x128) to fp16
__global__ void k_w12h(const float* __restrict__ W1, const float* __restrict__ Wmu,
                       const float* __restrict__ Wls) {
    int i = blockIdx.x * blockDim.x + threadIdx.x;
    if (i < 256 * HID) {
        g_W1h[i] = __float2half_rn(W1[i]);
    } else if (i < 256 * HID + HID * HID) {
        int j = i - 256 * HID;
        int k = j >> 7, c = j & 127;
        g_W2h[j] = __float2half_rn((c < 64) ? Wmu[k * 64 + c] : Wls[k * 64 + (c - 64)]);
    }
}

// ---------------- helpers ------------------------------------------------------
__device__ __forceinline__ void acc_h4(float4& a, uint2 u) {
    float2 lo = __half22float2(*reinterpret_cast<__half2*>(&u.x));
    float2 hi = __half22float2(*reinterpret_cast<__half2*>(&u.y));
    a.x += lo.x; a.y += lo.y; a.z += hi.x; a.w += hi.y;
}

// gather-sum over one node's in-edges; MLP-8 main loop
__device__ __forceinline__ float4 gather_sum(const uint2* __restrict__ Hs4,
                                             int node, int lane) {
    uint2 self = Hs4[(size_t)node * 32 + lane];
    float4 acc = make_float4(0.f, 0.f, 0.f, 0.f);
    acc_h4(acc, self);

    int e = g_rowstart[node];
    const int end = g_rowstart[node + 1];
    for (; e + 8 <= end; e += 8) {
        int s0 = g_csr_src[e + 0], s1 = g_csr_src[e + 1];
        int s2 = g_csr_src[e + 2], s3 = g_csr_src[e + 3];
        int s4 = g_csr_src[e + 4], s5 = g_csr_src[e + 5];
        int s6 = g_csr_src[e + 6], s7 = g_csr_src[e + 7];
        uint2 u0 = __ldg(&Hs4[(size_t)s0 * 32 + lane]);
        uint2 u1 = __ldg(&Hs4[(size_t)s1 * 32 + lane]);
        uint2 u2 = __ldg(&Hs4[(size_t)s2 * 32 + lane]);
        uint2 u3 = __ldg(&Hs4[(size_t)s3 * 32 + lane]);
        uint2 u4 = __ldg(&Hs4[(size_t)s4 * 32 + lane]);
        uint2 u5 = __ldg(&Hs4[(size_t)s5 * 32 + lane]);
        uint2 u6 = __ldg(&Hs4[(size_t)s6 * 32 + lane]);
        uint2 u7 = __ldg(&Hs4[(size_t)s7 * 32 + lane]);
        acc_h4(acc, u0); acc_h4(acc, u1); acc_h4(acc, u2); acc_h4(acc, u3);
        acc_h4(acc, u4); acc_h4(acc, u5); acc_h4(acc, u6); acc_h4(acc, u7);
    }
    for (; e + 2 <= end; e += 2) {
        int s0 = g_csr_src[e + 0], s1 = g_csr_src[e + 1];
        uint2 u0 = __ldg(&Hs4[(size_t)s0 * 32 + lane]);
        uint2 u1 = __ldg(&Hs4[(size_t)s1 * 32 + lane]);
        acc_h4(acc, u0); acc_h4(acc, u1);
    }
    if (e < end) {
        uint2 u = __ldg(&Hs4[(size_t)g_csr_src[e] * 32 + lane]);
        acc_h4(acc, u);
    }
    return acc;
}

// ---------------- aggregation (fp16 gather), one warp per node -----------------
// P[d,:] = dinv[d] * ( Hs[d,:] + sum_{edges s->d} Hs[s,:] )
// layer 1 variant: h = relu(P + b1), write fp16 (feeds tensor-core GEMM2)
__global__ __launch_bounds__(256) void k_agg_relu(int N, const float* __restrict__ b) {
    int warp = (blockIdx.x * blockDim.x + threadIdx.x) >> 5;
    int lane = threadIdx.x & 31;
    if (warp >= N) return;
    const int node = warp;
    float4 acc = gather_sum((const uint2*)g_Hs1, node, lane);

    float di = g_dinv[node];
    int c = lane * 4;
    float4 bb = *(const float4*)&b[c];
    __half2 h0 = __float22half2_rn(make_float2(fmaxf(acc.x * di + bb.x, 0.f),
                                               fmaxf(acc.y * di + bb.y, 0.f)));
    __half2 h1 = __float22half2_rn(make_float2(fmaxf(acc.z * di + bb.z, 0.f),
                                               fmaxf(acc.w * di + bb.w, 0.f)));
    uint2 pack;
    pack.x = *reinterpret_cast<unsigned*>(&h0);
    pack.y = *reinterpret_cast<unsigned*>(&h1);
    ((uint2*)g_hh)[(size_t)node * 32 + lane] = pack;
}

// layer 2 variant: split into (mu, logstd) halves with biases, write to output
__global__ __launch_bounds__(256) void k_agg_out(int N, const float* __restrict__ bmu,
                                                 const float* __restrict__ bls,
                                                 float* __restrict__ out) {
    int warp = (blockIdx.x * blockDim.x + threadIdx.x) >> 5;
    int lane = threadIdx.x & 31;
    if (warp >= N) return;
    const int node = warp;
    float4 acc = gather_sum((const uint2*)g_Hs2, node, lane);

    float di = g_dinv[node];
    int c = lane * 4;   // 0..124
    float4 r;
    if (c < 64) {
        float4 bb = *(const float4*)&bmu[c];
        r.x = acc.x * di + bb.x; r.y = acc.y * di + bb.y;
        r.z = acc.z * di + bb.z; r.w = acc.w * di + bb.w;
        *(float4*)&out[(size_t)node * 64 + c] = r;
    } else {
        float4 bb = *(const float4*)&bls[c - 64];
        r.x = acc.x * di + bb.x; r.y = acc.y * di + bb.y;
        r.z = acc.z * di + bb.z; r.w = acc.w * di + bb.w;
        *(float4*)&out[(size_t)N * 64 + (size_t)node * 64 + (c - 64)] = r;
    }
}

// ---------------- tensor-core GEMM: Hs[M,128] = fp16(dinv[m]*(A[M,K]@B[K,128]))
// BM=128, BN=128, BK=32. 256 threads = 8 warps in 4x2 grid; warp tile 32x64.
template<bool A_IS_HALF>
__global__ __launch_bounds__(256) void k_hgemm(int M, int K,
                                               const void* __restrict__ Av,
                                               const __half* __restrict__ B,
                                               __half* __restrict__ Hs) {
    constexpr int BM = 128, BN = 128, BK = 32;
    __shared__ __align__(32) __half As[BM][BK + 8];
    __shared__ __align__(32) __half Bs[BK][BN + 8];
    __shared__ __align__(32) float  Cs[8][16][24];

    const int tid = threadIdx.x;
    const int wid = tid >> 5;
    const int lane = tid & 31;
    const int warp_m = wid >> 1;          // 0..3
    const int warp_n = wid & 1;           // 0..1
    const int block_row = blockIdx.x * BM;

    wmma::fragment<wmma::accumulator, 16, 16, 16, float> facc[2][4];
    #pragma unroll
    for (int i = 0; i < 2; i++)
        #pragma unroll
        for (int j = 0; j < 4; j++) wmma::fill_fragment(facc[i][j], 0.0f);

    for (int k0 = 0; k0 < K; k0 += BK) {
        // ---- load A tile (128 x 32) ----
        if (A_IS_HALF) {
            const __half* A = (const __half*)Av;
            #pragma unroll
            for (int i = 0; i < 4; i++) {
                int idx = tid + i * 256;          // 0..1023
                int r = idx >> 3, c4 = (idx & 7) * 4;
                int gr = block_row + r;
                uint2 v = make_uint2(0u, 0u);
                if (gr < M) v = *(const uint2*)&A[(size_t)gr * K + k0 + c4];
                *(uint2*)&As[r][c4] = v;
            }
        } else {
            const float* A = (const float*)Av;
            #pragma unroll
            for (int i = 0; i < 4; i++) {
                int idx = tid + i * 256;
                int r = idx >> 3, c4 = (idx & 7) * 4;
                int gr = block_row + r;
                float4 v = make_float4(0.f, 0.f, 0.f, 0.f);
                if (gr < M) v = *(const float4*)&A[(size_t)gr * K + k0 + c4];
                __half2 h0 = __float22half2_rn(make_float2(v.x, v.y));
                __half2 h1 = __float22half2_rn(make_float2(v.z, v.w));
                uint2 pack;
                pack.x = *reinterpret_cast<unsigned*>(&h0);
                pack.y = *reinterpret_cast<unsigned*>(&h1);
                *(uint2*)&As[r][c4] = pack;
            }
        }
        // ---- load B tile (32 x 128) ----
        #pragma unroll
        for (int i = 0; i < 4; i++) {
            int idx = tid + i * 256;              // 0..1023
            int r = idx >> 5, c4 = (idx & 31) * 4;
            *(uint2*)&Bs[r][c4] = *(const uint2*)&B[(size_t)(k0 + r) * BN + c4];
        }
        __syncthreads();

        #pragma unroll
        for (int kk = 0; kk < BK; kk += 16) {
            wmma::fragment<wmma::matrix_a, 16, 16, 16, __half, wmma::row_major> fa[2];
            wmma::fragment<wmma::matrix_b, 16, 16, 16, __half, wmma::row_major> fb[4];
            #pragma unroll
            for (int i = 0; i < 2; i++)
                wmma::load_matrix_sync(fa[i], &As[warp_m * 32 + i * 16][kk], BK + 8);
            #pragma unroll
            for (int j = 0; j < 4; j++)
                wmma::load_matrix_sync(fb[j], &Bs[kk][warp_n * 64 + j * 16], BN + 8);
            #pragma unroll
            for (int i = 0; i < 2; i++)
                #pragma unroll
                for (int j = 0; j < 4; j++)
                    wmma::mma_sync(facc[i][j], fa[i], fb[j], facc[i][j]);
        }
        __syncthreads();
    }

    // ---- epilogue: scale rows by dinv, convert fp16, store ----
    #pragma unroll
    for (int i = 0; i < 2; i++) {
        #pragma unroll
        for (int j = 0; j < 4; j++) {
            wmma::store_matrix_sync(&Cs[wid][0][0], facc[i][j], 24, wmma::mem_row_major);
            __syncwarp();
            int r = lane >> 1;
            int gr = block_row + warp_m * 32 + i * 16 + r;
            int col = warp_n * 64 + j * 16 + (lane & 1) * 8;
            if (gr < M) {
                float di = g_dinv[gr];
                float4 v0 = *(float4*)&Cs[wid][r][(lane & 1) * 8];
                float4 v1 = *(float4*)&Cs[wid][r][(lane & 1) * 8 + 4];
                __half2 h0 = __float22half2_rn(make_float2(v0.x * di, v0.y * di));
                __half2 h1 = __float22half2_rn(make_float2(v0.z * di, v0.w * di));
                __half2 h2 = __float22half2_rn(make_float2(v1.x * di, v1.y * di));
                __half2 h3 = __float22half2_rn(make_float2(v1.z * di, v1.w * di));
                uint4 pack;
                pack.x = *reinterpret_cast<unsigned*>(&h0);
                pack.y = *reinterpret_cast<unsigned*>(&h1);
                pack.z = *reinterpret_cast<unsigned*>(&h2);
                pack.w = *reinterpret_cast<unsigned*>(&h3);
                *(uint4*)&Hs[(size_t)gr * BN + col] = pack;
            }
            __syncwarp();
        }
    }
}

// ---------------- launch ------------------------------------------------------
extern "C" void kernel_launch(void* const* d_in, const int* in_sizes, int n_in,
                              void* d_out, int out_size) {
    const float* x  = (const float*)d_in[0];
    const int*   ei = (const int*)d_in[1];
    int base = (n_in >= 9 && in_sizes[2] == 1) ? 3 : 2;
    const float* W1  = (const float*)d_in[base + 0];
    const float* b1  = (const float*)d_in[base + 1];
    const float* Wmu = (const float*)d_in[base + 2];
    const float* bmu = (const float*)d_in[base + 3];
    const float* Wls = (const float*)d_in[base + 4];
    const float* bls = (const float*)d_in[base + 5];
    float* out = (float*)d_out;

    const int N = in_sizes[0] / 256;   // 50000
    const int E = in_sizes[1] / 2;     // 1600000
    const int* src = ei;
    const int* dst = ei + E;

    __half *pHs1, *pHs2, *phh, *pW1h, *pW2h;
    int* pdeg;
    cudaGetSymbolAddress((void**)&pHs1, g_Hs1);
    cudaGetSymbolAddress((void**)&phh,  g_hh);
    cudaGetSymbolAddress((void**)&pHs2, g_Hs2);
    cudaGetSymbolAddress((void**)&pW1h, g_W1h);
    cudaGetSymbolAddress((void**)&pW2h, g_W2h);
    cudaGetSymbolAddress((void**)&pdeg, g_deg);

    // one-time side-stream + events (host resources, not device memory)
    static cudaStream_t s2 = nullptr;
    static cudaEvent_t ev_hist = nullptr, ev_csr = nullptr;
    if (!s2) {
        cudaStreamCreateWithFlags(&s2, cudaStreamNonBlocking);
        cudaEventCreateWithFlags(&ev_hist, cudaEventDisableTiming);
        cudaEventCreateWithFlags(&ev_csr, cudaEventDisableTiming);
    }

    const int T = 256;
    // ---- stream 0: deg histogram (needed by everything) ----
    cudaMemsetAsync(pdeg, 0, (size_t)N * sizeof(int), 0);
    k_hist_rank<<<(E + T - 1) / T, T>>>(dst, E);
    cudaEventRecord(ev_hist, 0);

    // ---- fork: stream s2 builds CSR (scan + scatter) ----
    cudaStreamWaitEvent(s2, ev_hist, 0);
    k_scan<<<1, 1024, 0, s2>>>(N);
    k_scatter<<<(E + T - 1) / T, T, 0, s2>>>(src, dst, E);
    cudaEventRecord(ev_csr, s2);

    // ---- stream 0 continues: dinv, weights, GEMM1 (overlaps CSR build) ----
    k_dinv<<<(N + T - 1) / T, T>>>(N);
    k_w12h<<<(256 * HID + HID * HID + T - 1) / T, T>>>(W1, Wmu, Wls);
    k_hgemm<false><<<(N + 127) / 128, 256>>>(N, 256, x, pW1h, pHs1);

    // ---- join, then the serial tail ----
    cudaStreamWaitEvent(0, ev_csr, 0);
    k_agg_relu<<<(N * 32 + T - 1) / T, T>>>(N, b1);
    k_hgemm<true><<<(N + 127) / 128, 256>>>(N, 128, phh, pW2h, pHs2);
    k_agg_out<<<(N * 32 + T - 1) / T, T>>>(N, bmu, bls, out);
}